// round 1
// baseline (speedup 1.0000x reference)
#include <cuda_runtime.h>

#define HD     64
#define VOC    64
#define HALF   32
#define BATCH  128
#define SEQLEN 2048
#define TSTEPS 2047   // scan runs over positions 0..L-2

// ---- scratch tables (device globals; no allocation allowed) ----
__device__ float g_ks[VOC * HALF];
__device__ float g_ke[VOC * HALF];
__device__ float g_inv_s[VOC];
__device__ float g_inv_e[VOC];

typedef unsigned long long u64;

// Packed f32x2 ops (Blackwell FFMA2 path — only reachable via PTX)
__device__ __forceinline__ u64 ffma2(u64 a, u64 b, u64 c) {
    u64 d;
    asm("fma.rn.f32x2 %0, %1, %2, %3;" : "=l"(d) : "l"(a), "l"(b), "l"(c));
    return d;
}
__device__ __forceinline__ u64 fadd2(u64 a, u64 b) {
    u64 d;
    asm("add.rn.f32x2 %0, %1, %2;" : "=l"(d) : "l"(a), "l"(b));
    return d;
}
__device__ __forceinline__ u64 pack2(float x, float y) {
    u64 r;
    asm("mov.b64 %0, {%1, %2};" : "=l"(r) : "f"(x), "f"(y));
    return r;
}
__device__ __forceinline__ float2 unpack2(u64 v) {
    float x, y;
    asm("mov.b64 {%0, %1}, %2;" : "=f"(x), "=f"(y) : "l"(v));
    return make_float2(x, y);
}

// ============================================================================
// Kernel A: per-vocab-id table precompute.
// h depends ONLY on the token id (embed lookup -> MLP -> residual -> LN is
// pointwise per token), so k_sem / k_epi / 1/den collapse to 64-entry tables.
// One block per vocab id, 128 threads.
// ============================================================================
__global__ void precompute_kernel(
    const float* __restrict__ embed,
    const float* __restrict__ W1, const float* __restrict__ b1,
    const float* __restrict__ W2, const float* __restrict__ b2,
    const float* __restrict__ ln_g, const float* __restrict__ ln_b,
    const float* __restrict__ Ws, const float* __restrict__ bs,
    const float* __restrict__ We, const float* __restrict__ be)
{
    const int v = blockIdx.x;
    const int t = threadIdx.x;

    __shared__ float s_e[HD];
    __shared__ float s_a[2 * HD];
    __shared__ float s_x[HD];
    __shared__ float s_h[HD];
    __shared__ float s_kv[2 * HALF];

    if (t < HD) s_e[t] = embed[v * HD + t];
    __syncthreads();

    // hidden = relu(e @ W1 + b1), 128 units, one per thread
    {
        float acc = b1[t];
        #pragma unroll
        for (int d = 0; d < HD; d++)
            acc = fmaf(s_e[d], W1[d * (2 * HD) + t], acc);
        s_a[t] = fmaxf(acc, 0.0f);
    }
    __syncthreads();

    // ff = hidden @ W2 + b2 ; x = e + ff
    if (t < HD) {
        float f = b2[t];
        #pragma unroll
        for (int k = 0; k < 2 * HD; k++)
            f = fmaf(s_a[k], W2[k * HD + t], f);
        s_x[t] = s_e[t] + f;
    }
    __syncthreads();

    // LayerNorm over the 64 features (computed redundantly per thread — tiny)
    if (t < HD) {
        float mu = 0.0f;
        #pragma unroll
        for (int d = 0; d < HD; d++) mu += s_x[d];
        mu *= (1.0f / HD);
        float var = 0.0f;
        #pragma unroll
        for (int d = 0; d < HD; d++) {
            float dd = s_x[d] - mu;
            var = fmaf(dd, dd, var);
        }
        var *= (1.0f / HD);
        float r = 1.0f / sqrtf(var + 1e-5f);
        s_h[t] = fmaf((s_x[t] - mu) * r, ln_g[t], ln_b[t]);
    }
    __syncthreads();

    // k_sem = h @ Ws + bs ; k_epi = h @ We + be
    if (t < HALF) {
        float k = bs[t];
        #pragma unroll
        for (int d = 0; d < HD; d++)
            k = fmaf(s_h[d], Ws[d * HALF + t], k);
        g_ks[v * HALF + t] = k;
        s_kv[t] = k;
    } else if (t < 2 * HALF) {
        const int j = t - HALF;
        float k = be[j];
        #pragma unroll
        for (int d = 0; d < HD; d++)
            k = fmaf(s_h[d], We[d * HALF + j], k);
        g_ke[v * HALF + j] = k;
        s_kv[t] = k;
    }
    __syncthreads();

    // Precompute 1/(k.k + 1e-6) — removes the division from the scan loop
    if (t == 0) {
        float den = 1e-6f;
        #pragma unroll
        for (int j = 0; j < HALF; j++) den = fmaf(s_kv[j], s_kv[j], den);
        g_inv_s[v] = 1.0f / den;
    } else if (t == 1) {
        float den = 1e-6f;
        #pragma unroll
        for (int j = 0; j < HALF; j++) den = fmaf(s_kv[HALF + j], s_kv[HALF + j], den);
        g_inv_e[v] = 1.0f / den;
    }
}

// ============================================================================
// Kernel B: the sequential scan. 128 blocks (one per batch), 2 warps each:
// warp 0 -> M_sem, warp 1 -> M_epi (fully independent until the epilogue).
// Lane i owns row i of its 32x32 M, stored as 16 packed f32x2 registers.
// Per step: matvec (16 FFMA2), dv = kown - vps*inv, rank-1 update (16 FFMA2).
// Next step's k-vector is prefetched during the update phase.
// ============================================================================
__global__ void __launch_bounds__(64, 1) scan_kernel(
    const int* __restrict__ seq,
    const float* __restrict__ Wo,
    const float* __restrict__ bo,
    float* __restrict__ out)
{
    const int b    = blockIdx.x;
    const int tid  = threadIdx.x;
    const int w    = tid >> 5;     // 0 = sem, 1 = epi
    const int lane = tid & 31;

    __shared__ int   s_tok[SEQLEN];
    __shared__ float s_k[2][VOC * HALF];
    __shared__ float s_inv[2][VOC];
    __shared__ float s_ctx[2 * HALF];

    for (int i = tid; i < SEQLEN; i += 64) s_tok[i] = seq[b * SEQLEN + i];
    for (int i = tid; i < VOC * HALF; i += 64) {
        s_k[0][i] = g_ks[i];
        s_k[1][i] = g_ke[i];
    }
    if (tid < VOC) {
        s_inv[0][tid] = g_inv_s[tid];
        s_inv[1][tid] = g_inv_e[tid];
    }
    __syncthreads();

    const float* ktab = s_k[w];
    const float* itab = s_inv[w];

    u64 m[16];
    #pragma unroll
    for (int j = 0; j < 16; j++) m[j] = 0ull;   // packed (0.0f, 0.0f)

    // prime the pipeline with token 0's k-vector
    int tok = s_tok[0];
    u64 k[16];
    {
        const u64* kp = (const u64*)(ktab + tok * HALF);
        #pragma unroll
        for (int j = 0; j < 16; j++) k[j] = kp[j];
    }
    float inv  = itab[tok];
    float kown = ktab[tok * HALF + lane];

    for (int t = 0; t < TSTEPS; t++) {
        // vps_i = sum_j M[i][j] * k[j]  (packed, 4 accumulators)
        u64 a0 = 0ull, a1 = 0ull, a2 = 0ull, a3 = 0ull;
        #pragma unroll
        for (int j = 0; j < 16; j += 4) {
            a0 = ffma2(m[j + 0], k[j + 0], a0);
            a1 = ffma2(m[j + 1], k[j + 1], a1);
            a2 = ffma2(m[j + 2], k[j + 2], a2);
            a3 = ffma2(m[j + 3], k[j + 3], a3);
        }
        float2 s = unpack2(fadd2(fadd2(a0, a1), fadd2(a2, a3)));
        float vps = s.x + s.y;

        float dv = fmaf(-vps, inv, kown);     // k_i - vps*inv
        if (w) dv *= (float)(t + 1) * (1.0f / 2048.0f);   // recency weight (epi only)
        u64 dv2 = pack2(dv, dv);

        // prefetch next token's data (index t+1; at t = TSTEPS-1 this loads
        // position L-1 = the query token, used by the final matvec below)
        const int tokn   = s_tok[t + 1];
        const float invn  = itab[tokn];
        const float kownn = ktab[tokn * HALF + lane];
        const u64* kpn   = (const u64*)(ktab + tokn * HALF);

        // rank-1 update, interleaved with prefetch loads
        #pragma unroll
        for (int j = 0; j < 16; j++) {
            m[j] = ffma2(dv2, k[j], m[j]);
            k[j] = kpn[j];
        }
        inv  = invn;
        kown = kownn;
    }

    // epilogue: k now holds the query token's projected vector (qs / qe)
    {
        u64 a0 = 0ull, a1 = 0ull, a2 = 0ull, a3 = 0ull;
        #pragma unroll
        for (int j = 0; j < 16; j += 4) {
            a0 = ffma2(m[j + 0], k[j + 0], a0);
            a1 = ffma2(m[j + 1], k[j + 1], a1);
            a2 = ffma2(m[j + 2], k[j + 2], a2);
            a3 = ffma2(m[j + 3], k[j + 3], a3);
        }
        float2 s = unpack2(fadd2(fadd2(a0, a1), fadd2(a2, a3)));
        s_ctx[w * HALF + lane] = s.x + s.y;   // [0..31]=ctx_s, [32..63]=ctx_e
    }
    __syncthreads();

    // out[b] = ctx @ Wo + bo   (thread tid = output column)
    float o = bo[tid];
    #pragma unroll
    for (int i = 0; i < 2 * HALF; i++)
        o = fmaf(s_ctx[i], Wo[i * VOC + tid], o);
    out[b * VOC + tid] = o;
}

// ============================================================================
// Launch. Inputs in metadata order:
// 0:seq 1:embed 2:W1 3:b1 4:W2 5:b2 6:ln_g 7:ln_b 8:Ws 9:bs 10:We 11:be 12:Wo 13:bo
// ============================================================================
extern "C" void kernel_launch(void* const* d_in, const int* in_sizes, int n_in,
                              void* d_out, int out_size)
{
    const int*   seq   = (const int*)  d_in[0];
    const float* embed = (const float*)d_in[1];
    const float* W1    = (const float*)d_in[2];
    const float* b1    = (const float*)d_in[3];
    const float* W2    = (const float*)d_in[4];
    const float* b2    = (const float*)d_in[5];
    const float* ln_g  = (const float*)d_in[6];
    const float* ln_b  = (const float*)d_in[7];
    const float* Ws    = (const float*)d_in[8];
    const float* bs    = (const float*)d_in[9];
    const float* We    = (const float*)d_in[10];
    const float* be    = (const float*)d_in[11];
    const float* Wo    = (const float*)d_in[12];
    const float* bo    = (const float*)d_in[13];

    precompute_kernel<<<VOC, 128>>>(embed, W1, b1, W2, b2, ln_g, ln_b,
                                    Ws, bs, We, be);
    scan_kernel<<<BATCH, 64>>>(seq, Wo, bo, (float*)d_out);
}

// round 2
// speedup vs baseline: 1.0801x; 1.0801x over previous
#include <cuda_runtime.h>

#define HD     64
#define VOC    64
#define HALF   32
#define BATCH  128
#define SEQLEN 2048
#define TSTEPS 2047   // scan runs over positions 0..L-2

// ---- scratch tables (device globals; no allocation allowed) ----
__device__ float g_ks[VOC * HALF];
__device__ float g_ke[VOC * HALF];
__device__ float g_inv_s[VOC];
__device__ float g_inv_e[VOC];
__device__ float g_Ds[VOC * VOC];   // D[v1][v2] = ks(v1) . ks(v2)
__device__ float g_De[VOC * VOC];   // D[v1][v2] = ke(v1) . ke(v2)

typedef unsigned long long u64;

// Packed f32x2 ops (Blackwell FFMA2 path — only reachable via PTX)
__device__ __forceinline__ u64 ffma2(u64 a, u64 b, u64 c) {
    u64 d;
    asm("fma.rn.f32x2 %0, %1, %2, %3;" : "=l"(d) : "l"(a), "l"(b), "l"(c));
    return d;
}
__device__ __forceinline__ u64 fadd2(u64 a, u64 b) {
    u64 d;
    asm("add.rn.f32x2 %0, %1, %2;" : "=l"(d) : "l"(a), "l"(b));
    return d;
}
__device__ __forceinline__ u64 pack2(float x, float y) {
    u64 r;
    asm("mov.b64 %0, {%1, %2};" : "=l"(r) : "f"(x), "f"(y));
    return r;
}
__device__ __forceinline__ float2 unpack2(u64 v) {
    float x, y;
    asm("mov.b64 {%0, %1}, %2;" : "=f"(x), "=f"(y) : "l"(v));
    return make_float2(x, y);
}

// ============================================================================
// Kernel A: per-vocab-id table precompute (h depends only on token id).
// ============================================================================
__global__ void precompute_kernel(
    const float* __restrict__ embed,
    const float* __restrict__ W1, const float* __restrict__ b1,
    const float* __restrict__ W2, const float* __restrict__ b2,
    const float* __restrict__ ln_g, const float* __restrict__ ln_b,
    const float* __restrict__ Ws, const float* __restrict__ bs,
    const float* __restrict__ We, const float* __restrict__ be)
{
    const int v = blockIdx.x;
    const int t = threadIdx.x;

    __shared__ float s_e[HD];
    __shared__ float s_a[2 * HD];
    __shared__ float s_x[HD];
    __shared__ float s_h[HD];
    __shared__ float s_kv[2 * HALF];

    if (t < HD) s_e[t] = embed[v * HD + t];
    __syncthreads();

    {   // hidden = relu(e @ W1 + b1), 128 units, one per thread
        float acc = b1[t];
        #pragma unroll
        for (int d = 0; d < HD; d++)
            acc = fmaf(s_e[d], W1[d * (2 * HD) + t], acc);
        s_a[t] = fmaxf(acc, 0.0f);
    }
    __syncthreads();

    if (t < HD) {   // ff = hidden @ W2 + b2 ; x = e + ff
        float f = b2[t];
        #pragma unroll
        for (int k = 0; k < 2 * HD; k++)
            f = fmaf(s_a[k], W2[k * HD + t], f);
        s_x[t] = s_e[t] + f;
    }
    __syncthreads();

    if (t < HD) {   // LayerNorm (redundant per thread — tiny)
        float mu = 0.0f;
        #pragma unroll
        for (int d = 0; d < HD; d++) mu += s_x[d];
        mu *= (1.0f / HD);
        float var = 0.0f;
        #pragma unroll
        for (int d = 0; d < HD; d++) {
            float dd = s_x[d] - mu;
            var = fmaf(dd, dd, var);
        }
        var *= (1.0f / HD);
        float r = 1.0f / sqrtf(var + 1e-5f);
        s_h[t] = fmaf((s_x[t] - mu) * r, ln_g[t], ln_b[t]);
    }
    __syncthreads();

    if (t < HALF) {             // k_sem = h @ Ws + bs
        float k = bs[t];
        #pragma unroll
        for (int d = 0; d < HD; d++)
            k = fmaf(s_h[d], Ws[d * HALF + t], k);
        g_ks[v * HALF + t] = k;
        s_kv[t] = k;
    } else if (t < 2 * HALF) {  // k_epi = h @ We + be
        const int j = t - HALF;
        float k = be[j];
        #pragma unroll
        for (int d = 0; d < HD; d++)
            k = fmaf(s_h[d], We[d * HALF + j], k);
        g_ke[v * HALF + j] = k;
        s_kv[t] = k;
    }
    __syncthreads();

    if (t == 0) {               // 1/(k.k + 1e-6)
        float den = 1e-6f;
        #pragma unroll
        for (int j = 0; j < HALF; j++) den = fmaf(s_kv[j], s_kv[j], den);
        g_inv_s[v] = 1.0f / den;
    } else if (t == 1) {
        float den = 1e-6f;
        #pragma unroll
        for (int j = 0; j < HALF; j++) den = fmaf(s_kv[HALF + j], s_kv[HALF + j], den);
        g_inv_e[v] = 1.0f / den;
    }
}

// ============================================================================
// Kernel A2: token-pair dot tables D[v1][v2] = k(v1).k(v2) per memory.
// grid=64, block=128: thread -> (mem = tid>>6, v2 = tid&63).
// ============================================================================
__global__ void dots_kernel()
{
    const int v1  = blockIdx.x;
    const int tid = threadIdx.x;
    const int v2  = tid & 63;
    const int mem = tid >> 6;

    const float* tab = mem ? g_ke : g_ks;
    float d = 0.0f;
    #pragma unroll
    for (int j = 0; j < HALF; j++)
        d = fmaf(tab[v1 * HALF + j], tab[v2 * HALF + j], d);
    (mem ? g_De : g_Ds)[v1 * VOC + v2] = d;
}

// ============================================================================
// Kernel B: the scan. 128 blocks (one per batch), 4 warps each:
//   warps 0,1 -> M_sem rows [0..15],[16..31]; warps 2,3 -> M_epi.
// Within a warp, 2 lanes per row: lane&1 selects the 16-column half.
// Lag-1 lookahead: iteration t computes
//   partial_{t+1} = M_{t-1} @ k_{t+1}   (after update M += u_{t-1} (x) k_{t-1})
//   vps_t = reduce(partial_t) + u_{t-1} * D[tok_{t-1}][tok_t]
// so the expensive matvec->reduce->shfl path spans 2 iterations of slack,
// while the true recurrence u_{t-1} -> vps_t -> u_t is 2 cheap FMAs.
// The final loop iteration's matvec targets tok[L-1] (the query token), so
// ctx = M_2046 @ q falls out of the epilogue reduce + correction.
// ============================================================================
__global__ void __launch_bounds__(128, 1) scan_kernel(
    const int* __restrict__ seq,
    const float* __restrict__ Wo,
    const float* __restrict__ bo,
    float* __restrict__ out)
{
    extern __shared__ int smem_raw[];
    int*   s_tok = smem_raw;                       // 2048 ints
    float* s_k   = (float*)(s_tok + SEQLEN);       // 2 * 2048 floats
    float* s_inv = s_k + 2 * VOC * HALF;           // 2 * 64
    float* s_D   = s_inv + 2 * VOC;                // 2 * 4096
    float* s_ctx = s_D + 2 * VOC * VOC;            // 64

    const int b    = blockIdx.x;
    const int tid  = threadIdx.x;
    const int wid  = tid >> 5;
    const int lane = tid & 31;
    const int mem   = wid >> 1;          // 0 = sem, 1 = epi
    const int whalf = wid & 1;           // row-half within the memory
    const int row   = whalf * 16 + (lane >> 1);
    const int ch    = lane & 1;          // column half (16 cols each)

    for (int i = tid; i < SEQLEN; i += 128) s_tok[i] = seq[b * SEQLEN + i];
    for (int i = tid; i < VOC * HALF; i += 128) {
        s_k[i]              = g_ks[i];
        s_k[VOC * HALF + i] = g_ke[i];
    }
    for (int i = tid; i < VOC * VOC; i += 128) {
        s_D[i]            = g_Ds[i];
        s_D[VOC * VOC + i] = g_De[i];
    }
    if (tid < VOC) {
        s_inv[tid]       = g_inv_s[tid];
        s_inv[VOC + tid] = g_inv_e[tid];
    }
    __syncthreads();

    const float* ktab = s_k + mem * (VOC * HALF);
    const float* itab = s_inv + mem * VOC;
    const float* Dtab = s_D + mem * (VOC * VOC);
    const int    coff = ch * 16;   // column offset of this lane's half-row

    u64 m[8];
    #pragma unroll
    for (int j = 0; j < 8; j++) m[j] = 0ull;

    // partial_0 accumulators (M_{-2} = 0 -> zeros)
    u64 a0 = 0ull, a1 = 0ull, a2 = 0ull, a3 = 0ull;

    float u_s = 0.0f;          // u_{t-1} scalar (this lane's row)
    u64   u2  = 0ull;          // packed (u, u)

    int   tok_prev = s_tok[0];   // dummy (u = 0 makes iter-0 update a no-op)
    int   tok_cur  = s_tok[0];
    float kown  = ktab[tok_cur * HALF + row];
    float inv   = itab[tok_cur];
    float Dprev = 0.0f;
    // epi: w_t = (t+1)/2048 (exact: multiples of 2^-11). sem: wt stays 1.
    float wt   = mem ? (1.0f / 2048.0f) : 1.0f;
    const float winc = mem ? (1.0f / 2048.0f) : 0.0f;

    for (int t = 0; t < TSTEPS; t++) {
        const int tok_next = s_tok[t + 1];

        // reload k_{t-1} (for update) and load k_{t+1} (for matvec): LDS.128 x8
        const ulonglong2* pu = (const ulonglong2*)(ktab + tok_prev * HALF + coff);
        const ulonglong2* pm = (const ulonglong2*)(ktab + tok_next * HALF + coff);
        ulonglong2 U0 = pu[0], U1 = pu[1], U2 = pu[2], U3 = pu[3];
        ulonglong2 N0 = pm[0], N1 = pm[1], N2 = pm[2], N3 = pm[3];

        // M += u_{t-1} (x) k_{t-1}   ->  M = M_{t-1}
        m[0] = ffma2(u2, U0.x, m[0]);
        m[1] = ffma2(u2, U0.y, m[1]);
        m[2] = ffma2(u2, U1.x, m[2]);
        m[3] = ffma2(u2, U1.y, m[3]);
        m[4] = ffma2(u2, U2.x, m[4]);
        m[5] = ffma2(u2, U2.y, m[5]);
        m[6] = ffma2(u2, U3.x, m[6]);
        m[7] = ffma2(u2, U3.y, m[7]);

        // reduce partial_t -> vps_t (with lag correction), then u_t
        u64 r0 = fadd2(a0, a1);
        u64 r1 = fadd2(a2, a3);
        float2 sred = unpack2(fadd2(r0, r1));
        float part = sred.x + sred.y;
        part += __shfl_xor_sync(0xffffffffu, part, 1);
        const float vps = fmaf(u_s, Dprev, part);
        const float dv  = fmaf(-vps, inv, kown);
        const float u   = dv * wt;
        u_s = u;
        u2  = pack2(u, u);

        // partial_{t+1} = M_{t-1} @ k_{t+1}
        a0 = ffma2(m[0], N0.x, 0ull);
        a1 = ffma2(m[1], N0.y, 0ull);
        a2 = ffma2(m[2], N1.x, 0ull);
        a3 = ffma2(m[3], N1.y, 0ull);
        a0 = ffma2(m[4], N2.x, a0);
        a1 = ffma2(m[5], N2.y, a1);
        a2 = ffma2(m[6], N3.x, a2);
        a3 = ffma2(m[7], N3.y, a3);

        // rotate scalars for t+1
        Dprev = Dtab[tok_cur * VOC + tok_next];
        kown  = ktab[tok_next * HALF + row];
        inv   = itab[tok_next];
        tok_prev = tok_cur;
        tok_cur  = tok_next;
        wt += winc;
    }

    // epilogue: partial accumulators now hold M_2045 @ q; correct with u_2046.
    {
        u64 r0 = fadd2(a0, a1);
        u64 r1 = fadd2(a2, a3);
        float2 sred = unpack2(fadd2(r0, r1));
        float part = sred.x + sred.y;
        part += __shfl_xor_sync(0xffffffffu, part, 1);
        const float ctx = fmaf(u_s, Dprev, part);   // = (M_2046 @ q)[row]
        if (ch == 0) s_ctx[mem * HALF + row] = ctx;
    }
    __syncthreads();

    // out[b] = ctx @ Wo + bo   (threads 0..63, one output column each)
    if (tid < VOC) {
        float o = bo[tid];
        #pragma unroll
        for (int i = 0; i < 2 * HALF; i++)
            o = fmaf(s_ctx[i], Wo[i * VOC + tid], o);
        out[b * VOC + tid] = o;
    }
}

// ============================================================================
// Launch. Inputs in metadata order:
// 0:seq 1:embed 2:W1 3:b1 4:W2 5:b2 6:ln_g 7:ln_b 8:Ws 9:bs 10:We 11:be 12:Wo 13:bo
// ============================================================================
#define SCAN_SMEM_BYTES ((SEQLEN + 2*VOC*HALF + 2*VOC + 2*VOC*VOC + VOC) * 4)

extern "C" void kernel_launch(void* const* d_in, const int* in_sizes, int n_in,
                              void* d_out, int out_size)
{
    const int*   seq   = (const int*)  d_in[0];
    const float* embed = (const float*)d_in[1];
    const float* W1    = (const float*)d_in[2];
    const float* b1    = (const float*)d_in[3];
    const float* W2    = (const float*)d_in[4];
    const float* b2    = (const float*)d_in[5];
    const float* ln_g  = (const float*)d_in[6];
    const float* ln_b  = (const float*)d_in[7];
    const float* Ws    = (const float*)d_in[8];
    const float* bs    = (const float*)d_in[9];
    const float* We    = (const float*)d_in[10];
    const float* be    = (const float*)d_in[11];
    const float* Wo    = (const float*)d_in[12];
    const float* bo    = (const float*)d_in[13];

    cudaFuncSetAttribute(scan_kernel,
                         cudaFuncAttributeMaxDynamicSharedMemorySize,
                         SCAN_SMEM_BYTES);

    precompute_kernel<<<VOC, 128>>>(embed, W1, b1, W2, b2, ln_g, ln_b,
                                    Ws, bs, We, be);
    dots_kernel<<<VOC, 128>>>();
    scan_kernel<<<BATCH, 128, SCAN_SMEM_BYTES>>>(seq, Wo, bo, (float*)d_out);
}

// round 3
// speedup vs baseline: 1.2110x; 1.1212x over previous
#include <cuda_runtime.h>

#define HD     64
#define VOC    64
#define HALF   32
#define BATCH  128
#define SEQLEN 2048

// ---- scratch tables (device globals; no allocation allowed) ----
__device__ float g_ks[VOC * HALF];
__device__ float g_ke[VOC * HALF];
__device__ float g_inv_s[VOC];
__device__ float g_inv_e[VOC];
__device__ float g_Ds[VOC * VOC];   // D[v1][v2] = ks(v1) . ks(v2)
__device__ float g_De[VOC * VOC];   // D[v1][v2] = ke(v1) . ke(v2)

typedef unsigned long long u64;

// Packed f32x2 ops (Blackwell FFMA2 path — only reachable via PTX)
__device__ __forceinline__ u64 ffma2(u64 a, u64 b, u64 c) {
    u64 d;
    asm("fma.rn.f32x2 %0, %1, %2, %3;" : "=l"(d) : "l"(a), "l"(b), "l"(c));
    return d;
}
__device__ __forceinline__ u64 fadd2(u64 a, u64 b) {
    u64 d;
    asm("add.rn.f32x2 %0, %1, %2;" : "=l"(d) : "l"(a), "l"(b));
    return d;
}
__device__ __forceinline__ u64 pack2(float x, float y) {
    u64 r;
    asm("mov.b64 %0, {%1, %2};" : "=l"(r) : "f"(x), "f"(y));
    return r;
}
__device__ __forceinline__ float2 unpack2(u64 v) {
    float x, y;
    asm("mov.b64 {%0, %1}, %2;" : "=f"(x), "=f"(y) : "l"(v));
    return make_float2(x, y);
}

// ============================================================================
// Kernel A: per-vocab-id table precompute (h depends only on token id).
// ============================================================================
__global__ void precompute_kernel(
    const float* __restrict__ embed,
    const float* __restrict__ W1, const float* __restrict__ b1,
    const float* __restrict__ W2, const float* __restrict__ b2,
    const float* __restrict__ ln_g, const float* __restrict__ ln_b,
    const float* __restrict__ Ws, const float* __restrict__ bs,
    const float* __restrict__ We, const float* __restrict__ be)
{
    const int v = blockIdx.x;
    const int t = threadIdx.x;

    __shared__ float s_e[HD];
    __shared__ float s_a[2 * HD];
    __shared__ float s_x[HD];
    __shared__ float s_h[HD];
    __shared__ float s_kv[2 * HALF];

    if (t < HD) s_e[t] = embed[v * HD + t];
    __syncthreads();

    {   // hidden = relu(e @ W1 + b1), 128 units, one per thread
        float acc = b1[t];
        #pragma unroll
        for (int d = 0; d < HD; d++)
            acc = fmaf(s_e[d], W1[d * (2 * HD) + t], acc);
        s_a[t] = fmaxf(acc, 0.0f);
    }
    __syncthreads();

    if (t < HD) {   // ff = hidden @ W2 + b2 ; x = e + ff
        float f = b2[t];
        #pragma unroll
        for (int k = 0; k < 2 * HD; k++)
            f = fmaf(s_a[k], W2[k * HD + t], f);
        s_x[t] = s_e[t] + f;
    }
    __syncthreads();

    if (t < HD) {   // LayerNorm (redundant per thread — tiny)
        float mu = 0.0f;
        #pragma unroll
        for (int d = 0; d < HD; d++) mu += s_x[d];
        mu *= (1.0f / HD);
        float var = 0.0f;
        #pragma unroll
        for (int d = 0; d < HD; d++) {
            float dd = s_x[d] - mu;
            var = fmaf(dd, dd, var);
        }
        var *= (1.0f / HD);
        float r = 1.0f / sqrtf(var + 1e-5f);
        s_h[t] = fmaf((s_x[t] - mu) * r, ln_g[t], ln_b[t]);
    }
    __syncthreads();

    if (t < HALF) {             // k_sem = h @ Ws + bs
        float k = bs[t];
        #pragma unroll
        for (int d = 0; d < HD; d++)
            k = fmaf(s_h[d], Ws[d * HALF + t], k);
        g_ks[v * HALF + t] = k;
        s_kv[t] = k;
    } else if (t < 2 * HALF) {  // k_epi = h @ We + be
        const int j = t - HALF;
        float k = be[j];
        #pragma unroll
        for (int d = 0; d < HD; d++)
            k = fmaf(s_h[d], We[d * HALF + j], k);
        g_ke[v * HALF + j] = k;
        s_kv[t] = k;
    }
    __syncthreads();

    if (t == 0) {               // 1/(k.k + 1e-6)
        float den = 1e-6f;
        #pragma unroll
        for (int j = 0; j < HALF; j++) den = fmaf(s_kv[j], s_kv[j], den);
        g_inv_s[v] = 1.0f / den;
    } else if (t == 1) {
        float den = 1e-6f;
        #pragma unroll
        for (int j = 0; j < HALF; j++) den = fmaf(s_kv[HALF + j], s_kv[HALF + j], den);
        g_inv_e[v] = 1.0f / den;
    }
}

// ============================================================================
// Kernel A2: token-pair dot tables D[v1][v2] = k(v1).k(v2) per memory.
// ============================================================================
__global__ void dots_kernel()
{
    const int v1  = blockIdx.x;
    const int tid = threadIdx.x;
    const int v2  = tid & 63;
    const int mem = tid >> 6;

    const float* tab = mem ? g_ke : g_ks;
    float d = 0.0f;
    #pragma unroll
    for (int j = 0; j < HALF; j++)
        d = fmaf(tab[v1 * HALF + j], tab[v2 * HALF + j], d);
    (mem ? g_De : g_Ds)[v1 * VOC + v2] = d;
}

// ============================================================================
// Kernel B: the scan, lag-2 lookahead.
// 128 blocks (one per batch), 4 warps: warps 0,1 -> M_sem halves, 2,3 -> M_epi.
// 2 lanes per row (lane&1 = 16-col half). Identity used:
//   vps_t = (M_{t-3} @ k_t) + u_{t-2} D[v_{t-2}][v_t] + u_{t-1} D[v_{t-1}][v_t]
// At iter t: update M += u_{t-1} (x) k_{t-1} (k from reg ring, loaded 3 iters
// ago); reduce the part-accumulator produced 2 iters ago; compute u_t with a
// single FMA (kw/iw pre-scaled by the recency weight one iter early); matvec
// M_{t-1} @ k_{t+2} into the alternate part buffer. Loop runs t=0..2047; iter
// 2047's vps IS ctx = M_2046 @ q (tok[L-1] is the query); its u is never used.
// ============================================================================
#define SCAN_STEP(T, KU, KL, P0, P1, CAP) do {                                 \
    const int offp2_ = s_toko[(T) + 4];                                        \
    const char* kp_ = kb_ch + offp2_;                                          \
    const ulonglong2 q0_ = *(const ulonglong2*)(kp_);                          \
    const ulonglong2 q1_ = *(const ulonglong2*)(kp_ + 16);                     \
    const ulonglong2 q2_ = *(const ulonglong2*)(kp_ + 32);                     \
    const ulonglong2 q3_ = *(const ulonglong2*)(kp_ + 48);                     \
    const int colb_ = off0 >> 5;                                               \
    const float Dm2_ = *(const float*)(Db + (offm2 << 1) + colb_);             \
    const float Dm1_ = *(const float*)(Db + (offm1 << 1) + colb_);             \
    const float ko2_ = *(const float*)(kob + offp2_);                          \
    const float iv2_ = *(const float*)(ivb + (offp2_ >> 5));                   \
    m[0] = ffma2(um1p, KU[0], m[0]); m[1] = ffma2(um1p, KU[1], m[1]);          \
    m[2] = ffma2(um1p, KU[2], m[2]); m[3] = ffma2(um1p, KU[3], m[3]);          \
    m[4] = ffma2(um1p, KU[4], m[4]); m[5] = ffma2(um1p, KU[5], m[5]);          \
    m[6] = ffma2(um1p, KU[6], m[6]); m[7] = ffma2(um1p, KU[7], m[7]);          \
    KL[0] = q0_.x; KL[1] = q0_.y; KL[2] = q1_.x; KL[3] = q1_.y;                \
    KL[4] = q2_.x; KL[5] = q2_.y; KL[6] = q3_.x; KL[7] = q3_.y;                \
    const float2 rs_ = unpack2(fadd2(P0, P1));                                 \
    float part_ = rs_.x + rs_.y;                                               \
    part_ += __shfl_xor_sync(0xffffffffu, part_, 1);                           \
    float vps_ = fmaf(um2, Dm2_, part_);                                       \
    vps_ = fmaf(um1, Dm1_, vps_);                                              \
    const float u_ = fmaf(-vps_, iw0, kw0);                                    \
    if (CAP) ctxv = vps_;                                                      \
    u64 t0_ = ffma2(m[0], KL[0], zero64);                                      \
    u64 t1_ = ffma2(m[1], KL[1], zero64);                                      \
    t0_ = ffma2(m[2], KL[2], t0_); t1_ = ffma2(m[3], KL[3], t1_);              \
    t0_ = ffma2(m[4], KL[4], t0_); t1_ = ffma2(m[5], KL[5], t1_);              \
    t0_ = ffma2(m[6], KL[6], t0_); t1_ = ffma2(m[7], KL[7], t1_);              \
    P0 = t0_; P1 = t1_;                                                        \
    um2 = um1; um1 = u_; um1p = pack2(u_, u_);                                 \
    kw0 = kw1; iw0 = iw1;                                                      \
    kw1 = ko2_ * wt2; iw1 = iv2_ * wt2; wt2 += winc;                           \
    offm2 = offm1; offm1 = off0; off0 = offp1; offp1 = offp2_;                 \
} while (0)

__global__ void __launch_bounds__(128, 1) scan_kernel(
    const int* __restrict__ seq,
    const float* __restrict__ Wo,
    const float* __restrict__ bo,
    float* __restrict__ out)
{
    extern __shared__ int smem_raw[];
    int*   s_toko = smem_raw;                        // 2052 ints (byte offsets)
    float* s_k    = (float*)(s_toko + 2052);         // 2 * 2048 floats
    float* s_inv  = s_k + 2 * VOC * HALF;            // 2 * 64
    float* s_D    = s_inv + 2 * VOC;                 // 2 * 4096
    float* s_ctx  = s_D + 2 * VOC * VOC;             // 64

    const int b    = blockIdx.x;
    const int tid  = threadIdx.x;
    const int wid  = tid >> 5;
    const int lane = tid & 31;
    const int mem   = wid >> 1;          // 0 = sem, 1 = epi
    const int whalf = wid & 1;
    const int row   = whalf * 16 + (lane >> 1);
    const int ch    = lane & 1;          // 16-column half

    for (int i = tid; i < SEQLEN; i += 128)
        s_toko[i + 2] = seq[b * SEQLEN + i] << 7;   // byte offset: tok*128
    if (tid < 2) { s_toko[tid] = 0; s_toko[2050 + tid] = 0; }
    for (int i = tid; i < VOC * HALF; i += 128) {
        s_k[i]              = g_ks[i];
        s_k[VOC * HALF + i] = g_ke[i];
    }
    for (int i = tid; i < VOC * VOC; i += 128) {
        s_D[i]             = g_Ds[i];
        s_D[VOC * VOC + i] = g_De[i];
    }
    if (tid < VOC) {
        s_inv[tid]       = g_inv_s[tid];
        s_inv[VOC + tid] = g_inv_e[tid];
    }
    __syncthreads();

    const float* ktab = s_k + mem * (VOC * HALF);
    const char*  kb_ch = (const char*)ktab + ch * 64;          // + tok*128
    const char*  kob   = (const char*)ktab + row * 4;          // kown base
    const char*  Db    = (const char*)(s_D + mem * (VOC * VOC));
    const char*  ivb   = (const char*)(s_inv + mem * VOC);

    const u64 zero64 = 0ull;
    u64 m[8];
    u64 kA[8], kB[8], kC[8], kD[8];    // ring slots 0..3
    #pragma unroll
    for (int j = 0; j < 8; j++) {
        m[j] = 0ull; kC[j] = 0ull; kD[j] = 0ull;
    }
    // prime ring: slot0 = k(tok_0), slot1 = k(tok_1)
    {
        const char* p0 = kb_ch + s_toko[2];
        const char* p1 = kb_ch + s_toko[3];
        #pragma unroll
        for (int j = 0; j < 4; j++) {
            ulonglong2 a = *(const ulonglong2*)(p0 + j * 16);
            ulonglong2 c = *(const ulonglong2*)(p1 + j * 16);
            kA[2 * j] = a.x; kA[2 * j + 1] = a.y;
            kB[2 * j] = c.x; kB[2 * j + 1] = c.y;
        }
    }

    u64 pA0 = 0ull, pA1 = 0ull, pB0 = 0ull, pB1 = 0ull;

    float um1 = 0.0f, um2 = 0.0f;
    u64   um1p = 0ull;
    float ctxv = 0.0f;

    int offm2 = s_toko[2], offm1 = s_toko[2];
    int off0  = s_toko[2], offp1 = s_toko[3];

    const float winc = mem ? (1.0f / 2048.0f) : 0.0f;
    const float w0   = mem ? (1.0f / 2048.0f) : 1.0f;
    const float w1   = mem ? (2.0f / 2048.0f) : 1.0f;
    float wt2        = mem ? (3.0f / 2048.0f) : 1.0f;

    float kw0 = *(const float*)(kob + off0)          * w0;
    float iw0 = *(const float*)(ivb + (off0 >> 5))   * w0;
    float kw1 = *(const float*)(kob + offp1)         * w1;
    float iw1 = *(const float*)(ivb + (offp1 >> 5))  * w1;

    for (int t = 0; t < 2048; t += 4) {
        SCAN_STEP(t + 0, kD, kC, pA0, pA1, 0);
        SCAN_STEP(t + 1, kA, kD, pB0, pB1, 0);
        SCAN_STEP(t + 2, kB, kA, pA0, pA1, 0);
        SCAN_STEP(t + 3, kC, kB, pB0, pB1, 1);
    }

    // ctxv (post-shfl, both lanes of a row-pair agree) = (M_2046 @ q)[row]
    if (ch == 0) s_ctx[mem * HALF + row] = ctxv;
    __syncthreads();

    if (tid < VOC) {
        float o = bo[tid];
        #pragma unroll
        for (int i = 0; i < 2 * HALF; i++)
            o = fmaf(s_ctx[i], Wo[i * VOC + tid], o);
        out[b * VOC + tid] = o;
    }
}

// ============================================================================
// Launch. Inputs in metadata order:
// 0:seq 1:embed 2:W1 3:b1 4:W2 5:b2 6:ln_g 7:ln_b 8:Ws 9:bs 10:We 11:be 12:Wo 13:bo
// ============================================================================
#define SCAN_SMEM_BYTES ((2052 + 2*VOC*HALF + 2*VOC + 2*VOC*VOC + VOC) * 4)

extern "C" void kernel_launch(void* const* d_in, const int* in_sizes, int n_in,
                              void* d_out, int out_size)
{
    const int*   seq   = (const int*)  d_in[0];
    const float* embed = (const float*)d_in[1];
    const float* W1    = (const float*)d_in[2];
    const float* b1    = (const float*)d_in[3];
    const float* W2    = (const float*)d_in[4];
    const float* b2    = (const float*)d_in[5];
    const float* ln_g  = (const float*)d_in[6];
    const float* ln_b  = (const float*)d_in[7];
    const float* Ws    = (const float*)d_in[8];
    const float* bs    = (const float*)d_in[9];
    const float* We    = (const float*)d_in[10];
    const float* be    = (const float*)d_in[11];
    const float* Wo    = (const float*)d_in[12];
    const float* bo    = (const float*)d_in[13];

    cudaFuncSetAttribute(scan_kernel,
                         cudaFuncAttributeMaxDynamicSharedMemorySize,
                         SCAN_SMEM_BYTES);

    precompute_kernel<<<VOC, 128>>>(embed, W1, b1, W2, b2, ln_g, ln_b,
                                    Ws, bs, We, be);
    dots_kernel<<<VOC, 128>>>();
    scan_kernel<<<BATCH, 128, SCAN_SMEM_BYTES>>>(seq, Wo, bo, (float*)d_out);
}